// round 8
// baseline (speedup 1.0000x reference)
#include <cuda_runtime.h>
#include <cstdint>

#define KTOP 2048
#define DD 128
#define HBINS 8192            // 13-bit key prefix
#define HSHIFT 19             // 32 - 13
#define CAND_MAX 4608
#define TPB 512
#define NB_CAP 1024
#define S_STAGES 4
#define TROWS 64
#define TBYTES 32768          // 64 rows * 512 B

// ---- static scratch (no allocations allowed) ----
__device__ unsigned int g_hist[HBINS];
__device__ float g_y[500224];
__device__ unsigned int g_cnt;
__device__ unsigned int g_done;
__device__ __align__(16) unsigned long long g_cand[CAND_MAX];
__device__ unsigned int g_bar_count;
__device__ volatile unsigned int g_bar_gen;

// monotonic unsigned key for f32 ordering
__device__ __forceinline__ unsigned int fkey(float f) {
    unsigned int u = __float_as_uint(f);
    return (u & 0x80000000u) ? ~u : (u | 0x80000000u);
}
__device__ __forceinline__ float dot4(float4 a, float4 b) {
    return a.x * b.x + a.y * b.y + a.z * b.z + a.w * b.w;
}

// ---- mbarrier / bulk-async helpers ----
__device__ __forceinline__ unsigned int sm2u(const void* p) {
    return (unsigned int)__cvta_generic_to_shared(p);
}
__device__ __forceinline__ void mb_init(unsigned int a, unsigned int cnt) {
    asm volatile("mbarrier.init.shared.b64 [%0], %1;" :: "r"(a), "r"(cnt) : "memory");
}
__device__ __forceinline__ void mb_expect(unsigned int a, unsigned int bytes) {
    asm volatile("mbarrier.arrive.expect_tx.shared.b64 _, [%0], %1;"
                 :: "r"(a), "r"(bytes) : "memory");
}
__device__ __forceinline__ void bulk_g2s(unsigned int dst, const void* src,
                                         unsigned int bytes, unsigned int mbar) {
    asm volatile(
        "cp.async.bulk.shared::cluster.global.mbarrier::complete_tx::bytes "
        "[%0], [%1], %2, [%3];"
        :: "r"(dst), "l"(src), "r"(bytes), "r"(mbar) : "memory");
}
__device__ __forceinline__ void mb_wait(unsigned int a, unsigned int ph) {
    asm volatile(
        "{\n\t.reg .pred P1;\n\t"
        "WAIT_LOOP_%=:\n\t"
        "mbarrier.try_wait.parity.acquire.cta.shared::cta.b64 P1, [%0], %1, 0x989680;\n\t"
        "@P1 bra.uni WAIT_DONE_%=;\n\t"
        "bra.uni WAIT_LOOP_%=;\n\t"
        "WAIT_DONE_%=:\n\t}"
        :: "r"(a), "r"(ph) : "memory");
}

// software grid barrier (1 block/SM -> co-resident)
__device__ __forceinline__ void grid_bar(int nb) {
    __threadfence();
    __syncthreads();
    if (threadIdx.x == 0) {
        unsigned int gen = g_bar_gen;
        if (atomicAdd(&g_bar_count, 1u) == (unsigned int)(nb - 1)) {
            g_bar_count = 0u;
            __threadfence();
            g_bar_gen = gen + 1u;
        } else {
            while (g_bar_gen == gen) { __nanosleep(64); }
        }
    }
    __syncthreads();
}

__device__ __forceinline__ void try_push(float y, int i, unsigned int tb) {
    unsigned int key = fkey(y);
    if ((key >> HSHIFT) >= tb) {
        unsigned int pos = atomicAdd(&g_cnt, 1u);
        if (pos < CAND_MAX) {
            // value-descending major, index-ascending minor
            g_cand[pos] = ((unsigned long long)key << 32) |
                          (unsigned long long)(~(unsigned int)i);
        }
    }
}

__global__ void __launch_bounds__(TPB, 1)
mega(const float* __restrict__ x, const float* __restrict__ p,
     float* __restrict__ out, int n, int nb)
{
    const int tid = threadIdx.x;
    const int lane = tid & 31;
    const int l8 = lane & 7;
    const int wib = tid >> 5;
    const int gtid = blockIdx.x * TPB + tid;
    const int gthreads = nb * TPB;

    extern __shared__ __align__(1024) unsigned char dynbuf[];   // 4 x 32 KB stages
    unsigned long long* sk = reinterpret_cast<unsigned long long*>(dynbuf);

    __shared__ unsigned int shist[HBINS];   // 32 KB
    __shared__ unsigned long long mbar[S_STAGES];
    __shared__ unsigned int ss[512];
    __shared__ unsigned int swt[16], saf[16];
    __shared__ unsigned int s_tbin;
    __shared__ int s_rk[64];
    __shared__ int s_ridx[64];
    __shared__ float s_rt[64];

    const unsigned int dyn_u = sm2u(dynbuf);
    const unsigned int mb_u = sm2u(mbar);

    // ---- phase 0: norm (per-warp, registers only) ----
    const float4* __restrict__ p4 = reinterpret_cast<const float4*>(p);
    float4 q0 = p4[l8], q1 = p4[l8 + 8], q2 = p4[l8 + 16], q3 = p4[l8 + 24];
    float s2 = (dot4(q0, q0) + dot4(q1, q1)) + (dot4(q2, q2) + dot4(q3, q3));
    s2 += __shfl_xor_sync(0xffffffffu, s2, 1);
    s2 += __shfl_xor_sync(0xffffffffu, s2, 2);
    s2 += __shfl_xor_sync(0xffffffffu, s2, 4);
    const float inv = 1.0f / sqrtf(s2);

    // ---- phase 1: TMA-pipelined dot ----
    for (int i = tid; i < HBINS; i += TPB) shist[i] = 0u;
    if (tid == 0) {
        #pragma unroll
        for (int s = 0; s < S_STAGES; s++) mb_init(mb_u + s * 8, 1u);
    }
    __syncthreads();

    const int ntiles = n >> 6;                 // 64-row tiles
    const int b = blockIdx.x;
    const int mytiles = (b < ntiles) ? ((ntiles - 1 - b) / nb + 1) : 0;
    const char* __restrict__ xb = reinterpret_cast<const char*>(x);

    if (tid == 0) {
        int pre = mytiles < S_STAGES ? mytiles : S_STAGES;
        for (int k = 0; k < pre; k++) {
            int gt = b + k * nb;
            mb_expect(mb_u + k * 8, TBYTES);
            bulk_g2s(dyn_u + k * TBYTES, xb + (size_t)gt * TBYTES, TBYTES, mb_u + k * 8);
        }
    }

    const int myrow = tid >> 3;                // 0..63, one row per 8-lane group
    for (int i = 0; i < mytiles; i++) {
        int s = i & (S_STAGES - 1);
        unsigned int ph = (i >> 2) & 1u;
        mb_wait(mb_u + s * 8, ph);

        const float4* row4 = reinterpret_cast<const float4*>(
            dynbuf + s * TBYTES + myrow * 512);
        float4 v0 = row4[l8], v1 = row4[l8 + 8], v2 = row4[l8 + 16], v3 = row4[l8 + 24];
        float sA = (dot4(v0, q0) + dot4(v1, q1)) + (dot4(v2, q2) + dot4(v3, q3));
        sA += __shfl_xor_sync(0xffffffffu, sA, 1);
        sA += __shfl_xor_sync(0xffffffffu, sA, 2);
        sA += __shfl_xor_sync(0xffffffffu, sA, 4);
        if (l8 == 0) {
            int gt = b + i * nb;
            int r = gt * TROWS + myrow;
            float y = sA * inv;
            g_y[r] = y;
            atomicAdd(&shist[fkey(y) >> HSHIFT], 1u);
        }
        __syncthreads();
        if (tid == 0 && i + S_STAGES < mytiles) {
            int gt2 = b + (i + S_STAGES) * nb;
            mb_expect(mb_u + s * 8, TBYTES);
            bulk_g2s(dyn_u + s * TBYTES, xb + (size_t)gt2 * TBYTES, TBYTES, mb_u + s * 8);
        }
    }

    // tail rows [ntiles*64, n): block 0 / warp 0, full-width dot from gmem
    const float4* __restrict__ x4 = reinterpret_cast<const float4*>(x);
    const int n64 = ntiles * TROWS;
    if (blockIdx.x == 0 && tid < 32 && n64 < n) {
        float4 pl = p4[lane];
        for (int r = n64; r < n; r++) {
            float4 v = x4[(size_t)r * 32 + lane];
            float s = dot4(v, pl);
            #pragma unroll
            for (int o = 16; o; o >>= 1) s += __shfl_xor_sync(0xffffffffu, s, o);
            if (lane == 0) {
                float y = s * inv;
                g_y[r] = y;
                atomicAdd(&shist[fkey(y) >> HSHIFT], 1u);
            }
        }
    }
    __syncthreads();
    for (int i = tid; i < HBINS; i += TPB) {
        unsigned int v = shist[i];
        if (v) atomicAdd(&g_hist[i], v);
    }
    grid_bar(nb);

    // ---- phase 2 (every block, redundant): find threshold bin ----
    {
        const uint4* h4 = reinterpret_cast<const uint4*>(g_hist) + tid * 4;
        uint4 a = h4[0], bq = h4[1], c = h4[2], d = h4[3];
        unsigned int part = a.x + a.y + a.z + a.w + bq.x + bq.y + bq.z + bq.w
                          + c.x + c.y + c.z + c.w + d.x + d.y + d.z + d.w;
        unsigned int s = part;
        #pragma unroll
        for (int off = 1; off < 32; off <<= 1) {
            unsigned int v = __shfl_down_sync(0xffffffffu, s, off);
            if (lane + off < 32) s += v;
        }
        if (lane == 0) swt[wib] = s;
        __syncthreads();
        if (tid < 16) {
            unsigned int acc = 0;
            for (int i = tid + 1; i < 16; i++) acc += swt[i];
            saf[tid] = acc;
        }
        __syncthreads();
        unsigned int incl = s + saf[wib];
        unsigned int nxt = incl - part;
        if (incl >= KTOP && nxt < KTOP) {
            unsigned int acc = nxt;
            for (int bi = tid * 16 + 15; bi >= tid * 16; bi--) {
                acc += g_hist[bi];
                if (acc >= KTOP) { s_tbin = (unsigned int)bi; break; }
            }
        }
        __syncthreads();
    }

    // ---- phase 3: compact candidates (whole grid, one float4/thread) ----
    {
        unsigned int tb = s_tbin;
        int n4 = n >> 2;
        const float4* __restrict__ y4 = reinterpret_cast<const float4*>(g_y);
        for (int i = gtid; i < n4; i += gthreads) {
            float4 v = y4[i];
            try_push(v.x, i * 4 + 0, tb);
            try_push(v.y, i * 4 + 1, tb);
            try_push(v.z, i * 4 + 2, tb);
            try_push(v.w, i * 4 + 3, tb);
        }
        if (gtid == 0) {
            for (int j = n & ~3; j < n; j++) try_push(g_y[j], j, tb);
        }
    }
    grid_bar(nb);

    // ---- phase 4 (fused rank + gather + write): 64 candidates/block ----
    {
        int C = (int)min(g_cnt, (unsigned int)CAND_MAX);
        int nactive = (C + 63) >> 6;
        if (blockIdx.x < nactive) {
            for (int i = tid; i < C; i += TPB) sk[i] = g_cand[i];
            __syncthreads();
            if (tid == 0) {
                if (atomicAdd(&g_done, 1u) + 1u == (unsigned int)nactive) {
                    g_cnt = 0u;
                    g_done = 0u;
                }
            }
            int j = tid & 63;
            int seg = tid >> 6;        // 8 segments
            int jg = blockIdx.x * 64 + j;
            unsigned long long pk = (jg < C) ? sk[jg] : ~0ull;
            int segsz = (C + 7) >> 3;
            int lo = seg * segsz;
            int hi = lo + segsz; if (hi > C) hi = C;
            int part = 0;
            int i = lo;
            for (; i + 4 <= hi; i += 4) {
                part += (sk[i + 0] > pk);
                part += (sk[i + 1] > pk);
                part += (sk[i + 2] > pk);
                part += (sk[i + 3] > pk);
            }
            for (; i < hi; i++) part += (sk[i] > pk);
            ss[tid] = (unsigned int)part;
            __syncthreads();
            if (tid < 64) {
                int rk = -1, idx = 0;
                float tv = 0.f;
                if (jg < C) {
                    int rank = (int)(ss[tid] + ss[tid + 64] + ss[tid + 128] +
                                     ss[tid + 192] + ss[tid + 256] + ss[tid + 320] +
                                     ss[tid + 384] + ss[tid + 448]);
                    if (rank < KTOP) {
                        unsigned int key = (unsigned int)(pk >> 32);
                        unsigned int u = (key & 0x80000000u) ? (key ^ 0x80000000u) : ~key;
                        rk = rank;
                        idx = (int)(~(unsigned int)(pk & 0xFFFFFFFFull));
                        tv = tanhf(__uint_as_float(u));
                    }
                }
                s_rk[tid] = rk;
                s_ridx[tid] = idx;
                s_rt[tid] = tv;
            }
            __syncthreads();
            {
                int c = tid >> 3;
                int sg = tid & 7;
                int rk = s_rk[c];
                if (rk >= 0) {
                    int idx = s_ridx[c];
                    float tv = s_rt[c];
                    const float4* xr = x4 + (size_t)idx * 32 + sg;
                    float4* orow = reinterpret_cast<float4*>(out) + (size_t)rk * 32 + sg;
                    float4 v0 = xr[0], v1 = xr[8], v2 = xr[16], v3 = xr[24];
                    orow[0]  = make_float4(v0.x * tv, v0.y * tv, v0.z * tv, v0.w * tv);
                    orow[8]  = make_float4(v1.x * tv, v1.y * tv, v1.z * tv, v1.w * tv);
                    orow[16] = make_float4(v2.x * tv, v2.y * tv, v2.z * tv, v2.w * tv);
                    orow[24] = make_float4(v3.x * tv, v3.y * tv, v3.z * tv, v3.w * tv);
                }
            }
        }
    }

    // ---- replay-state reset (no barrier needed: kernel end syncs) ----
    for (int i = gtid; i < HBINS; i += gthreads) g_hist[i] = 0u;
}

extern "C" void kernel_launch(void* const* d_in, const int* in_sizes, int n_in,
                              void* d_out, int out_size) {
    const float* x = (const float*)d_in[0];
    const float* p = (const float*)d_in[1];
    int n = in_sizes[0] / DD;

    const int DSMEM = S_STAGES * TBYTES;   // 128 KB
    cudaFuncSetAttribute(mega, cudaFuncAttributeMaxDynamicSharedMemorySize, DSMEM);

    int dev = 0;
    cudaGetDevice(&dev);
    int sm = 0;
    cudaDeviceGetAttribute(&sm, cudaDevAttrMultiProcessorCount, dev);
    int bpsm = 0;
    cudaOccupancyMaxActiveBlocksPerMultiprocessor(&bpsm, mega, TPB, DSMEM);
    if (bpsm < 1) bpsm = 1;
    int nb = sm * bpsm;
    if (nb > NB_CAP) nb = NB_CAP;

    mega<<<nb, TPB, DSMEM>>>(x, p, (float*)d_out, n, nb);
}

// round 9
// speedup vs baseline: 1.2115x; 1.2115x over previous
#include <cuda_runtime.h>
#include <cstdint>

#define KTOP 2048
#define DD 128
#define HBINS 8192            // 13-bit key prefix
#define HSHIFT 19             // 32 - 13
#define CAND_MAX 4608
#define TPB 256
#define NB_CAP 1024

// ---- static scratch (no allocations allowed) ----
__device__ unsigned int g_hist[HBINS];
__device__ float g_y[500224];
__device__ unsigned int g_cnt;
__device__ unsigned int g_done;
__device__ __align__(16) unsigned long long g_cand[CAND_MAX];
__device__ unsigned int g_bar_count;
__device__ volatile unsigned int g_bar_gen;

// monotonic unsigned key for f32 ordering
__device__ __forceinline__ unsigned int fkey(float f) {
    unsigned int u = __float_as_uint(f);
    return (u & 0x80000000u) ? ~u : (u | 0x80000000u);
}
__device__ __forceinline__ float dot4(float4 a, float4 b) {
    return a.x * b.x + a.y * b.y + a.z * b.z + a.w * b.w;
}

// software grid barrier (all blocks co-resident by construction)
__device__ __forceinline__ void grid_bar(int nb) {
    __threadfence();
    __syncthreads();
    if (threadIdx.x == 0) {
        unsigned int gen = g_bar_gen;
        if (atomicAdd(&g_bar_count, 1u) == (unsigned int)(nb - 1)) {
            g_bar_count = 0u;
            __threadfence();
            g_bar_gen = gen + 1u;
        } else {
            while (g_bar_gen == gen) { __nanosleep(64); }
        }
    }
    __syncthreads();
}

__device__ __forceinline__ void try_push(float y, int i, unsigned int tb) {
    unsigned int key = fkey(y);
    if ((key >> HSHIFT) >= tb) {
        unsigned int pos = atomicAdd(&g_cnt, 1u);
        if (pos < CAND_MAX) {
            // value-descending major, index-ascending minor
            g_cand[pos] = ((unsigned long long)key << 32) |
                          (unsigned long long)(~(unsigned int)i);
        }
    }
}

// load 8 float4 for row-pair starting at r (rows r+grp, r+grp+4)
#define LOAD8(c0,c1,c2,c3,c4,c5,c6,c7, r) do {                               \
    const float4* _xa = x4 + (size_t)((r) + grp) * 32 + l8;                  \
    const float4* _xb = _xa + 4 * 32;                                        \
    c0 = __ldcs(_xa + 0);  c1 = __ldcs(_xa + 8);                             \
    c2 = __ldcs(_xa + 16); c3 = __ldcs(_xa + 24);                            \
    c4 = __ldcs(_xb + 0);  c5 = __ldcs(_xb + 8);                             \
    c6 = __ldcs(_xb + 16); c7 = __ldcs(_xb + 24);                            \
} while (0)

#define COMP8(c0,c1,c2,c3,c4,c5,c6,c7, r) do {                               \
    float sA = (dot4(c0, q0) + dot4(c1, q1)) + (dot4(c2, q2) + dot4(c3, q3));\
    float sB = (dot4(c4, q0) + dot4(c5, q1)) + (dot4(c6, q2) + dot4(c7, q3));\
    sA += __shfl_xor_sync(0xffffffffu, sA, 1);                               \
    sB += __shfl_xor_sync(0xffffffffu, sB, 1);                               \
    sA += __shfl_xor_sync(0xffffffffu, sA, 2);                               \
    sB += __shfl_xor_sync(0xffffffffu, sB, 2);                               \
    sA += __shfl_xor_sync(0xffffffffu, sA, 4);                               \
    sB += __shfl_xor_sync(0xffffffffu, sB, 4);                               \
    if (l8 == 0) {                                                           \
        int _rA = (r) + grp;                                                 \
        float yA = sA * inv;                                                 \
        float yB = sB * inv;                                                 \
        g_y[_rA] = yA;                                                       \
        g_y[_rA + 4] = yB;                                                   \
        atomicAdd(&shist[fkey(yA) >> HSHIFT], 1u);                           \
        atomicAdd(&shist[fkey(yB) >> HSHIFT], 1u);                           \
    }                                                                        \
} while (0)

__global__ void __launch_bounds__(TPB, 2)
mega(const float* __restrict__ x, const float* __restrict__ p,
     float* __restrict__ out, int n, int nb)
{
    const int tid = threadIdx.x;
    const int lane = tid & 31;
    const int l8 = lane & 7;
    const int grp = lane >> 3;
    const int wib = tid >> 5;              // warp in block (8)
    const int gtid = blockIdx.x * TPB + tid;
    const int gthreads = nb * TPB;
    const int wid = gtid >> 5;
    const int nw = gthreads >> 5;

    // union: phase-1 smem histogram (8192 u32 = 32 KB) / phase-4 keys (4608 u64 = 36.9 KB)
    __shared__ __align__(16) unsigned char sbuf[36864];
    unsigned int* shist = reinterpret_cast<unsigned int*>(sbuf);
    unsigned long long* sk = reinterpret_cast<unsigned long long*>(sbuf);
    __shared__ unsigned int ss[TPB];
    __shared__ unsigned int swt[8], saf[8];
    __shared__ unsigned int s_tbin;
    __shared__ int s_rk[64];
    __shared__ int s_ridx[64];
    __shared__ float s_rt[64];

    // ---- phase 0: norm (per-warp, registers only) ----
    const float4* __restrict__ p4 = reinterpret_cast<const float4*>(p);
    float4 q0 = p4[l8], q1 = p4[l8 + 8], q2 = p4[l8 + 16], q3 = p4[l8 + 24];
    float s2 = (dot4(q0, q0) + dot4(q1, q1)) + (dot4(q2, q2) + dot4(q3, q3));
    s2 += __shfl_xor_sync(0xffffffffu, s2, 1);
    s2 += __shfl_xor_sync(0xffffffffu, s2, 2);
    s2 += __shfl_xor_sync(0xffffffffu, s2, 4);
    const float inv = 1.0f / sqrtf(s2);

    // ---- phase 1: software-pipelined coalesced dot, private smem hist ----
    for (int i = tid; i < HBINS; i += TPB) shist[i] = 0u;
    __syncthreads();

    const float4* __restrict__ x4 = reinterpret_cast<const float4*>(x);
    const int n8 = n & ~7;
    const int stride = nw * 8;
    {
        const int wbase = wid * 8;
        int niter = (wbase < n8) ? ((n8 - 1 - wbase) / stride + 1) : 0;
        float4 a0, a1, a2, a3, a4, a5, a6, a7;
        float4 b0, b1, b2, b3, b4, b5, b6, b7;
        if (niter > 0) LOAD8(a0,a1,a2,a3,a4,a5,a6,a7, wbase);
        int i = 0;
        // unroll-by-2 ping-pong: next iter's loads issued before current compute
        for (; i + 2 <= niter; i += 2) {
            int rcur = wbase + i * stride;
            int rmid = rcur + stride;
            int rnxt = rmid + stride;
            LOAD8(b0,b1,b2,b3,b4,b5,b6,b7, rmid);
            COMP8(a0,a1,a2,a3,a4,a5,a6,a7, rcur);
            if (i + 2 < niter) LOAD8(a0,a1,a2,a3,a4,a5,a6,a7, rnxt);
            COMP8(b0,b1,b2,b3,b4,b5,b6,b7, rmid);
        }
        if (i < niter) {
            int rcur = wbase + i * stride;
            COMP8(a0,a1,a2,a3,a4,a5,a6,a7, rcur);
        }
    }
    // tail rows [n8, n): block 0 / warp 0, full-width dot
    if (blockIdx.x == 0 && tid < 32 && n8 < n) {
        float4 pl = p4[lane];
        for (int r = n8; r < n; r++) {
            float4 v = x4[(size_t)r * 32 + lane];
            float s = dot4(v, pl);
            #pragma unroll
            for (int o = 16; o; o >>= 1) s += __shfl_xor_sync(0xffffffffu, s, o);
            if (lane == 0) {
                float y = s * inv;
                g_y[r] = y;
                atomicAdd(&shist[fkey(y) >> HSHIFT], 1u);
            }
        }
    }
    __syncthreads();
    for (int i = tid; i < HBINS; i += TPB) {
        unsigned int v = shist[i];
        if (v) atomicAdd(&g_hist[i], v);
    }
    grid_bar(nb);

    // ---- phase 2 (every block, redundant): find threshold bin ----
    {
        const uint4* h4 = reinterpret_cast<const uint4*>(g_hist) + tid * 8;
        unsigned int part = 0;
        #pragma unroll
        for (int i = 0; i < 8; i++) {
            uint4 a = h4[i];
            part += a.x + a.y + a.z + a.w;
        }
        unsigned int s = part;
        #pragma unroll
        for (int off = 1; off < 32; off <<= 1) {
            unsigned int v = __shfl_down_sync(0xffffffffu, s, off);
            if (lane + off < 32) s += v;
        }
        if (lane == 0) swt[wib] = s;
        __syncthreads();
        if (tid < 8) {
            unsigned int acc = 0;
            for (int i = tid + 1; i < 8; i++) acc += swt[i];
            saf[tid] = acc;
        }
        __syncthreads();
        unsigned int incl = s + saf[wib];
        unsigned int nxt = incl - part;
        if (incl >= KTOP && nxt < KTOP) {
            unsigned int acc = nxt;
            for (int bi = tid * 32 + 31; bi >= tid * 32; bi--) {
                acc += g_hist[bi];
                if (acc >= KTOP) { s_tbin = (unsigned int)bi; break; }
            }
        }
        __syncthreads();
    }

    // ---- phase 3: compact candidates (whole grid, one float4/thread) ----
    {
        unsigned int tb = s_tbin;
        int n4 = n >> 2;
        const float4* __restrict__ y4 = reinterpret_cast<const float4*>(g_y);
        for (int i = gtid; i < n4; i += gthreads) {
            float4 v = y4[i];
            try_push(v.x, i * 4 + 0, tb);
            try_push(v.y, i * 4 + 1, tb);
            try_push(v.z, i * 4 + 2, tb);
            try_push(v.w, i * 4 + 3, tb);
        }
        if (gtid == 0) {
            for (int j = n & ~3; j < n; j++) try_push(g_y[j], j, tb);
        }
    }
    grid_bar(nb);

    // ---- phase 4 (fused rank + gather + write): 64 candidates/block ----
    {
        int C = (int)min(g_cnt, (unsigned int)CAND_MAX);
        int nactive = (C + 63) >> 6;
        if (blockIdx.x < nactive) {
            for (int i = tid; i < C; i += TPB) sk[i] = g_cand[i];
            __syncthreads();
            // all threads of this block have read g_cnt; handshake the reset
            if (tid == 0) {
                if (atomicAdd(&g_done, 1u) + 1u == (unsigned int)nactive) {
                    g_cnt = 0u;
                    g_done = 0u;
                }
            }
            int j = tid & 63;
            int seg = tid >> 6;        // 4 segments
            int jg = blockIdx.x * 64 + j;
            unsigned long long pk = (jg < C) ? sk[jg] : ~0ull;
            int segsz = (C + 3) >> 2;
            int lo = seg * segsz;
            int hi = lo + segsz; if (hi > C) hi = C;
            int part = 0;
            int i = lo;
            for (; i + 4 <= hi; i += 4) {
                part += (sk[i + 0] > pk);
                part += (sk[i + 1] > pk);
                part += (sk[i + 2] > pk);
                part += (sk[i + 3] > pk);
            }
            for (; i < hi; i++) part += (sk[i] > pk);
            ss[tid] = (unsigned int)part;
            __syncthreads();
            if (tid < 64) {
                int rk = -1, idx = 0;
                float tv = 0.f;
                if (jg < C) {
                    int rank = (int)(ss[tid] + ss[tid + 64] +
                                     ss[tid + 128] + ss[tid + 192]);
                    if (rank < KTOP) {
                        unsigned int key = (unsigned int)(pk >> 32);
                        unsigned int u = (key & 0x80000000u) ? (key ^ 0x80000000u) : ~key;
                        rk = rank;
                        idx = (int)(~(unsigned int)(pk & 0xFFFFFFFFull));
                        tv = tanhf(__uint_as_float(u));
                    }
                }
                s_rk[tid] = rk;
                s_ridx[tid] = idx;
                s_rt[tid] = tv;
            }
            __syncthreads();
            // gather + write: 8 threads per candidate, 2 passes of 32 candidates
            #pragma unroll
            for (int c0 = 0; c0 < 64; c0 += 32) {
                int c = c0 + (tid >> 3);
                int sg = tid & 7;
                int rk = s_rk[c];
                if (rk >= 0) {
                    int idx = s_ridx[c];
                    float tv = s_rt[c];
                    const float4* xr = x4 + (size_t)idx * 32 + sg;
                    float4* orow = reinterpret_cast<float4*>(out) + (size_t)rk * 32 + sg;
                    float4 v0 = xr[0], v1 = xr[8], v2 = xr[16], v3 = xr[24];
                    orow[0]  = make_float4(v0.x * tv, v0.y * tv, v0.z * tv, v0.w * tv);
                    orow[8]  = make_float4(v1.x * tv, v1.y * tv, v1.z * tv, v1.w * tv);
                    orow[16] = make_float4(v2.x * tv, v2.y * tv, v2.z * tv, v2.w * tv);
                    orow[24] = make_float4(v3.x * tv, v3.y * tv, v3.z * tv, v3.w * tv);
                }
            }
        }
    }

    // ---- replay-state reset (no barrier needed: kernel end syncs) ----
    for (int i = gtid; i < HBINS; i += gthreads) g_hist[i] = 0u;
}

extern "C" void kernel_launch(void* const* d_in, const int* in_sizes, int n_in,
                              void* d_out, int out_size) {
    const float* x = (const float*)d_in[0];
    const float* p = (const float*)d_in[1];
    int n = in_sizes[0] / DD;

    int dev = 0;
    cudaGetDevice(&dev);
    int sm = 0;
    cudaDeviceGetAttribute(&sm, cudaDevAttrMultiProcessorCount, dev);
    int bpsm = 0;
    cudaOccupancyMaxActiveBlocksPerMultiprocessor(&bpsm, mega, TPB, 0);
    if (bpsm < 1) bpsm = 1;
    int nb = sm * bpsm;
    if (nb > NB_CAP) nb = NB_CAP;

    mega<<<nb, TPB>>>(x, p, (float*)d_out, n, nb);
}

// round 10
// speedup vs baseline: 1.3845x; 1.1429x over previous
#include <cuda_runtime.h>
#include <cstdint>

#define KTOP 2048
#define DD 128
#define HBINS 8192            // 13-bit key prefix (fallback path)
#define HSHIFT 19
#define CAND_MAX 6144
#define TS_VAL 2.42f          // speculative threshold; exact path verifies bounds
#define TPB 512
#define NB_CAP 1024

// ---- static scratch (no allocations allowed) ----
__device__ unsigned int g_hist[HBINS];          // fallback only (kept zeroed)
__device__ float g_y[500224];
__device__ unsigned int g_cnt;
__device__ unsigned int g_cnt2;
__device__ unsigned int g_done;
__device__ __align__(16) unsigned long long g_cand[CAND_MAX];
__device__ unsigned int g_bar_count;
__device__ volatile unsigned int g_bar_gen;

// monotonic unsigned key for f32 ordering
__device__ __forceinline__ unsigned int fkey(float f) {
    unsigned int u = __float_as_uint(f);
    return (u & 0x80000000u) ? ~u : (u | 0x80000000u);
}
__device__ __forceinline__ float dot4(float4 a, float4 b) {
    return a.x * b.x + a.y * b.y + a.z * b.z + a.w * b.w;
}

// software grid barrier (all blocks co-resident by construction)
__device__ __forceinline__ void grid_bar(int nb) {
    __threadfence();
    __syncthreads();
    if (threadIdx.x == 0) {
        unsigned int gen = g_bar_gen;
        if (atomicAdd(&g_bar_count, 1u) == (unsigned int)(nb - 1)) {
            g_bar_count = 0u;
            __threadfence();
            g_bar_gen = gen + 1u;
        } else {
            while (g_bar_gen == gen) { __nanosleep(64); }
        }
    }
    __syncthreads();
}

__device__ __forceinline__ void push_cand(float y, int i, unsigned int* cnt) {
    unsigned int key = fkey(y);
    unsigned int pos = atomicAdd(cnt, 1u);
    if (pos < CAND_MAX) {
        // value-descending major, index-ascending minor
        g_cand[pos] = ((unsigned long long)key << 32) |
                      (unsigned long long)(~(unsigned int)i);
    }
}

__global__ void __launch_bounds__(TPB, 2)
mega(const float* __restrict__ x, const float* __restrict__ p,
     float* __restrict__ out, int n, int nb)
{
    const int tid = threadIdx.x;
    const int lane = tid & 31;
    const int l8 = lane & 7;
    const int grp = lane >> 3;
    const int wib = tid >> 5;
    const int gtid = blockIdx.x * TPB + tid;
    const int gthreads = nb * TPB;
    const int wid = gtid >> 5;
    const int nw = gthreads >> 5;

    // union: phase-4 keys (6144 u64 = 48 KB) / fallback smem hist (8192 u32 = 32 KB)
    __shared__ __align__(16) unsigned char sbuf[CAND_MAX * 8];
    unsigned long long* sk = reinterpret_cast<unsigned long long*>(sbuf);
    unsigned int* shist = reinterpret_cast<unsigned int*>(sbuf);
    __shared__ unsigned int ss[TPB];
    __shared__ unsigned int swt[16], saf[16];
    __shared__ unsigned int s_tbin;
    __shared__ int s_rk[64];
    __shared__ int s_ridx[64];
    __shared__ float s_rt[64];

    // ---- phase 0: norm (per-warp, registers only) ----
    const float4* __restrict__ p4 = reinterpret_cast<const float4*>(p);
    float4 q0 = p4[l8], q1 = p4[l8 + 8], q2 = p4[l8 + 16], q3 = p4[l8 + 24];
    float s2 = (dot4(q0, q0) + dot4(q1, q1)) + (dot4(q2, q2) + dot4(q3, q3));
    s2 += __shfl_xor_sync(0xffffffffu, s2, 1);
    s2 += __shfl_xor_sync(0xffffffffu, s2, 2);
    s2 += __shfl_xor_sync(0xffffffffu, s2, 4);
    const float inv = 1.0f / sqrtf(s2);

    // ---- phase 1: coalesced dot + immediate speculative candidate push ----
    const float4* __restrict__ x4 = reinterpret_cast<const float4*>(x);
    const int n8 = n & ~7;
    for (int r0 = wid * 8; r0 < n8; r0 += nw * 8) {
        int rA = r0 + grp;
        const float4* xa = x4 + (size_t)rA * 32 + l8;
        const float4* xb = xa + 4 * 32;
        float4 a0 = __ldcs(xa + 0), a1 = __ldcs(xa + 8),
               a2 = __ldcs(xa + 16), a3 = __ldcs(xa + 24);
        float4 b0 = __ldcs(xb + 0), b1 = __ldcs(xb + 8),
               b2 = __ldcs(xb + 16), b3 = __ldcs(xb + 24);
        float sA = (dot4(a0, q0) + dot4(a1, q1)) + (dot4(a2, q2) + dot4(a3, q3));
        float sB = (dot4(b0, q0) + dot4(b1, q1)) + (dot4(b2, q2) + dot4(b3, q3));
        sA += __shfl_xor_sync(0xffffffffu, sA, 1);
        sB += __shfl_xor_sync(0xffffffffu, sB, 1);
        sA += __shfl_xor_sync(0xffffffffu, sA, 2);
        sB += __shfl_xor_sync(0xffffffffu, sB, 2);
        sA += __shfl_xor_sync(0xffffffffu, sA, 4);
        sB += __shfl_xor_sync(0xffffffffu, sB, 4);
        if (l8 == 0) {
            float yA = sA * inv;
            float yB = sB * inv;
            g_y[rA] = yA;
            g_y[rA + 4] = yB;
            if (yA >= TS_VAL) push_cand(yA, rA, &g_cnt);
            if (yB >= TS_VAL) push_cand(yB, rA + 4, &g_cnt);
        }
    }
    // tail rows [n8, n): block 0 / warp 0
    if (blockIdx.x == 0 && tid < 32 && n8 < n) {
        float4 pl = p4[lane];
        for (int r = n8; r < n; r++) {
            float4 v = x4[(size_t)r * 32 + lane];
            float s = dot4(v, pl);
            #pragma unroll
            for (int o = 16; o; o >>= 1) s += __shfl_xor_sync(0xffffffffu, s, o);
            if (lane == 0) {
                float y = s * inv;
                g_y[r] = y;
                if (y >= TS_VAL) push_cand(y, r, &g_cnt);
            }
        }
    }
    grid_bar(nb);

    unsigned int c1 = g_cnt;
    // handshake: reset g_cnt once every block has read it
    if (tid == 0) {
        if (atomicAdd(&g_done, 1u) + 1u == (unsigned int)nb) {
            g_cnt = 0u;
            g_done = 0u;
        }
    }

    int C;
    if (c1 >= KTOP && c1 <= CAND_MAX) {
        C = (int)c1;                       // fast path: candidates complete
    } else {
        // ===== fallback (exact, rare): histogram -> threshold -> compact =====
        for (int i = tid; i < HBINS; i += TPB) shist[i] = 0u;
        __syncthreads();
        for (int r = gtid; r < n; r += gthreads)
            atomicAdd(&shist[fkey(g_y[r]) >> HSHIFT], 1u);
        __syncthreads();
        for (int i = tid; i < HBINS; i += TPB) {
            unsigned int v = shist[i];
            if (v) atomicAdd(&g_hist[i], v);
        }
        grid_bar(nb);
        // threshold bin (every block, redundant)
        {
            const uint4* h4 = reinterpret_cast<const uint4*>(g_hist) + tid * 4;
            uint4 a = h4[0], b = h4[1], c = h4[2], d = h4[3];
            unsigned int part = a.x + a.y + a.z + a.w + b.x + b.y + b.z + b.w
                              + c.x + c.y + c.z + c.w + d.x + d.y + d.z + d.w;
            unsigned int s = part;
            #pragma unroll
            for (int off = 1; off < 32; off <<= 1) {
                unsigned int v = __shfl_down_sync(0xffffffffu, s, off);
                if (lane + off < 32) s += v;
            }
            if (lane == 0) swt[wib] = s;
            __syncthreads();
            if (tid < 16) {
                unsigned int acc = 0;
                for (int i = tid + 1; i < 16; i++) acc += swt[i];
                saf[tid] = acc;
            }
            __syncthreads();
            unsigned int incl = s + saf[wib];
            unsigned int nxt = incl - part;
            if (incl >= KTOP && nxt < KTOP) {
                unsigned int acc = nxt;
                for (int bi = tid * 16 + 15; bi >= tid * 16; bi--) {
                    acc += g_hist[bi];
                    if (acc >= KTOP) { s_tbin = (unsigned int)bi; break; }
                }
            }
            __syncthreads();
        }
        // compact using exact bin threshold
        {
            unsigned int tb = s_tbin;
            for (int r = gtid; r < n; r += gthreads) {
                float y = g_y[r];
                if ((fkey(y) >> HSHIFT) >= tb) push_cand(y, r, &g_cnt2);
            }
        }
        grid_bar(nb);
        unsigned int c2 = g_cnt2;
        if (tid == 0) {
            if (atomicAdd(&g_done, 1u) + 1u == (unsigned int)nb) {
                g_cnt2 = 0u;
                g_done = 0u;
            }
        }
        for (int i = tid; i < HBINS; i += TPB) shist[i] = 0u;   // clear union before sk use
        for (int i = gtid; i < HBINS; i += gthreads) g_hist[i] = 0u;
        C = (int)min(c2, (unsigned int)CAND_MAX);
        grid_bar(nb);      // hist reads done & cand writes visible before rank
    }

    // ---- rank + gather + write (fused): 64 candidates/block ----
    {
        int nactive = (C + 63) >> 6;
        if (blockIdx.x < nactive) {
            for (int i = tid; i < C; i += TPB) sk[i] = g_cand[i];
            __syncthreads();
            int j = tid & 63;
            int seg = tid >> 6;            // 8 segments
            int jg = blockIdx.x * 64 + j;
            unsigned long long pk = (jg < C) ? sk[jg] : ~0ull;
            int segsz = (C + 7) >> 3;
            int lo = seg * segsz;
            int hi = lo + segsz; if (hi > C) hi = C;
            int part = 0;
            int i = lo;
            for (; i + 4 <= hi; i += 4) {
                part += (sk[i + 0] > pk);
                part += (sk[i + 1] > pk);
                part += (sk[i + 2] > pk);
                part += (sk[i + 3] > pk);
            }
            for (; i < hi; i++) part += (sk[i] > pk);
            ss[tid] = (unsigned int)part;
            __syncthreads();
            if (tid < 64) {
                int rk = -1, idx = 0;
                float tv = 0.f;
                if (jg < C) {
                    int rank = (int)(ss[tid] + ss[tid + 64] + ss[tid + 128] +
                                     ss[tid + 192] + ss[tid + 256] + ss[tid + 320] +
                                     ss[tid + 384] + ss[tid + 448]);
                    if (rank < KTOP) {
                        unsigned int key = (unsigned int)(pk >> 32);
                        unsigned int u = (key & 0x80000000u) ? (key ^ 0x80000000u) : ~key;
                        rk = rank;
                        idx = (int)(~(unsigned int)(pk & 0xFFFFFFFFull));
                        tv = tanhf(__uint_as_float(u));
                    }
                }
                s_rk[tid] = rk;
                s_ridx[tid] = idx;
                s_rt[tid] = tv;
            }
            __syncthreads();
            // gather + write: 8 threads per candidate
            {
                int c = tid >> 3;
                int sg = tid & 7;
                int rk = s_rk[c];
                if (rk >= 0) {
                    int idx = s_ridx[c];
                    float tv = s_rt[c];
                    const float4* xr = x4 + (size_t)idx * 32 + sg;
                    float4* orow = reinterpret_cast<float4*>(out) + (size_t)rk * 32 + sg;
                    float4 v0 = xr[0], v1 = xr[8], v2 = xr[16], v3 = xr[24];
                    orow[0]  = make_float4(v0.x * tv, v0.y * tv, v0.z * tv, v0.w * tv);
                    orow[8]  = make_float4(v1.x * tv, v1.y * tv, v1.z * tv, v1.w * tv);
                    orow[16] = make_float4(v2.x * tv, v2.y * tv, v2.z * tv, v2.w * tv);
                    orow[24] = make_float4(v3.x * tv, v3.y * tv, v3.z * tv, v3.w * tv);
                }
            }
        }
    }
}

extern "C" void kernel_launch(void* const* d_in, const int* in_sizes, int n_in,
                              void* d_out, int out_size) {
    const float* x = (const float*)d_in[0];
    const float* p = (const float*)d_in[1];
    int n = in_sizes[0] / DD;

    int dev = 0;
    cudaGetDevice(&dev);
    int sm = 0;
    cudaDeviceGetAttribute(&sm, cudaDevAttrMultiProcessorCount, dev);
    int bpsm = 0;
    cudaOccupancyMaxActiveBlocksPerMultiprocessor(&bpsm, mega, TPB, 0);
    if (bpsm < 1) bpsm = 1;
    int nb = sm * bpsm;
    if (nb > NB_CAP) nb = NB_CAP;

    mega<<<nb, TPB>>>(x, p, (float*)d_out, n, nb);
}